// round 14
// baseline (speedup 1.0000x reference)
#include <cuda_runtime.h>
#include <cuda_fp16.h>
#include <cstdint>

#define MAXN 100000
#define MAXE 1600000
#define HD 128
#define SLOPE 0.2f
#define SCAN_B 1024

// ---------------- scratch (device globals) ----------------
__device__ __half g_xp1h[(size_t)MAXN * HD];   // layer1 x@W1 in fp16
__device__ float g_es[MAXN];
__device__ float g_ed[MAXN];
__device__ float g_xp2[MAXN];
__device__ int   g_cs[MAXE];
__device__ int   g_cd[MAXE];
__device__ int   g_csr[MAXE];
__device__ int   g_deg[MAXN];      // re-zeroed each run by k_scanC
__device__ int   g_cur[MAXN];
__device__ int   g_scan[MAXN];
__device__ int   g_rowptr[MAXN + 1];
__device__ int   g_bsum[128];
__device__ int   g_boff[128];
__device__ int   g_cnt;            // re-zeroed each run by k_node1
__device__ unsigned g_tick;        // reset by scanA's last block

// ---------------- helpers ----------------
__device__ __forceinline__ float lrelu(float x) { return x > 0.f ? x : SLOPE * x; }

__device__ __forceinline__ uint32_t f2tf32(float f) {
    uint32_t r; asm("cvt.rna.tf32.f32 %0, %1;" : "=r"(r) : "f"(f)); return r;
}

__device__ __forceinline__ uint32_t f2h2(float a, float b) {
    __half2 h = __floats2half2_rn(a, b);
    return *(uint32_t*)&h;
}

__device__ __forceinline__ void mma_tf32(float* c, const uint32_t* a, const uint32_t* b) {
    asm volatile("mma.sync.aligned.m16n8k8.row.col.f32.tf32.tf32.f32 "
                 "{%0,%1,%2,%3}, {%4,%5,%6,%7}, {%8,%9}, {%0,%1,%2,%3};"
                 : "+f"(c[0]), "+f"(c[1]), "+f"(c[2]), "+f"(c[3])
                 : "r"(a[0]), "r"(a[1]), "r"(a[2]), "r"(a[3]), "r"(b[0]), "r"(b[1]));
}

// fp16 row gather: 4 dims per lane as uint2 -> float4 (fp32 math)
__device__ __forceinline__ float4 gather_h4(int row, int lane) {
    uint2 u = __ldg((const uint2*)&g_xp1h[(size_t)row * HD] + lane);
    float2 lo = __half22float2(*(__half2*)&u.x);
    float2 hi = __half22float2(*(__half2*)&u.y);
    return make_float4(lo.x, lo.y, hi.x, hi.y);
}

// ---------------- compact + degree ----------------
__global__ void k_deg(const int* __restrict__ ei, const int* __restrict__ nt, int E) {
    int Er = (E + 31) & ~31;
    int lane = threadIdx.x & 31;
    int stride = gridDim.x * blockDim.x;
    for (int i = blockIdx.x * blockDim.x + threadIdx.x; i < Er; i += stride) {
        int s = 0, d = 0;
        bool act = false;
        if (i < E) {
            s = ei[i];
            d = ei[E + i];
            act = (__ldg(&nt[s]) == 0) && (__ldg(&nt[d]) == 0);
        }
        unsigned ball = __ballot_sync(0xffffffffu, act);
        if (ball) {
            int leader = __ffs(ball) - 1;
            int base = 0;
            if (lane == leader) base = atomicAdd(&g_cnt, __popc(ball));
            base = __shfl_sync(0xffffffffu, base, leader);
            if (act) {
                int off = __popc(ball & ((1u << lane) - 1u));
                g_cs[base + off] = s;
                g_cd[base + off] = d;
                atomicAdd(&g_deg[d], 1);
            }
        }
    }
}

// ---------------- scan ----------------
__global__ void __launch_bounds__(SCAN_B) k_scanA(int N) {
    __shared__ int wsum[32];
    __shared__ bool isLast;
    int tid = threadIdx.x;
    int lane = tid & 31;
    int wid = tid >> 5;
    int i = blockIdx.x * SCAN_B + tid;
    int v = (i < N) ? g_deg[i] : 0;

#pragma unroll
    for (int off = 1; off < 32; off <<= 1) {
        int t = __shfl_up_sync(0xffffffffu, v, off);
        if (lane >= off) v += t;
    }
    if (lane == 31) wsum[wid] = v;
    __syncthreads();
    if (wid == 0) {
        int w = wsum[lane];
#pragma unroll
        for (int off = 1; off < 32; off <<= 1) {
            int t = __shfl_up_sync(0xffffffffu, w, off);
            if (lane >= off) w += t;
        }
        wsum[lane] = w;
    }
    __syncthreads();
    if (wid) v += wsum[wid - 1];

    if (i < N) g_scan[i] = v;
    if (tid == SCAN_B - 1) g_bsum[blockIdx.x] = v;

    __threadfence();
    __syncthreads();
    if (tid == 0) {
        unsigned t = atomicAdd(&g_tick, 1u);
        isLast = (t == gridDim.x - 1);
    }
    __syncthreads();
    if (isLast && wid == 0) {
        int nb = gridDim.x;
        int total = 0;
        for (int c = 0; c * 32 < nb; c++) {
            int idx = c * 32 + lane;
            int x = (idx < nb) ? g_bsum[idx] : 0;
#pragma unroll
            for (int off = 1; off < 32; off <<= 1) {
                int t2 = __shfl_up_sync(0xffffffffu, x, off);
                if (lane >= off) x += t2;
            }
            if (idx < nb) g_boff[idx] = x + total;
            total += __shfl_sync(0xffffffffu, x, 31);
        }
        if (lane == 0) g_tick = 0;
        __threadfence();
    }
}

__global__ void k_scanC(int N) {
    int i = blockIdx.x * blockDim.x + threadIdx.x;
    if (i < N) {
        int b = i >> 10;
        int off = b ? g_boff[b - 1] : 0;
        int incl = off + g_scan[i];
        g_rowptr[i + 1] = incl;
        g_cur[i] = incl - g_deg[i];
        g_deg[i] = 0;
        if (i == 0) g_rowptr[0] = 0;
    }
}

__global__ void k_scatter() {
    int cnt = g_cnt;
    int st = gridDim.x * blockDim.x;
    for (int i = blockIdx.x * blockDim.x + threadIdx.x; i < cnt; i += st) {
        int s = g_cs[i], d = g_cd[i];
        int pos = atomicAdd(&g_cur[d], 1);
        g_csr[pos] = s;
    }
}

// =======================================================================
// GEMM1: xp1 = emb[h] @ W1 via mma.sync tf32 (m16n8k8).
// CTA = 64m x 128n, 8 warps (2m x 4n), warp tile 32x32 -> 32 accs/thread,
// 3 CTAs/SM (occupancy fix). Direct half2 global stores (no epilogue smem
// round-trip); es/ed via quad-shuffle + smem atomic reduction.
// =======================================================================
static constexpr int MPAD = 72;    // A row pad (words) for [k][m]
static constexpr int KPAD = 136;   // B row pad (words) for [k][n]

__global__ void __launch_bounds__(256, 3)
k_gemm1_tc(const int* __restrict__ hidx, const float* __restrict__ emb,
           const float* __restrict__ W,
           const float* __restrict__ as1, const float* __restrict__ ad1, int N)
{
    __shared__ uint32_t xs[32 * MPAD];   // A chunk [k][m] 32k x 64m
    __shared__ uint32_t ws[32 * KPAD];   // B chunk [k][n] 32k x 128n
    __shared__ float es_s[64], ed_s[64];

    int tid  = threadIdx.x;
    int lane = tid & 31;
    int wid  = tid >> 5;
    int g    = lane >> 2;
    int tg   = lane & 3;
    int m_base = (wid & 1) * 32;
    int n_base = (wid >> 1) * 32;
    int blk0 = blockIdx.x * 64;

    if (tid < 64) { es_s[tid] = 0.f; ed_s[tid] = 0.f; }

    float acc[2][4][4];
#pragma unroll
    for (int mf = 0; mf < 2; mf++)
#pragma unroll
        for (int nf = 0; nf < 4; nf++)
#pragma unroll
            for (int q = 0; q < 4; q++) acc[mf][nf][q] = 0.f;

    // A gather mapping: row = tid/4 (64 rows), quarter = tid%4 (2 float4 each)
    int arow = tid >> 2;
    int aq = tid & 3;
    int grow = blk0 + arow;
    int hrow = (grow < N) ? __ldg(&hidx[grow]) : 0;
    const float4* aptr = (const float4*)&emb[(size_t)hrow * HD];

    int bkk = tid >> 3;
    int bseg = tid & 7;

    for (int kc = 0; kc < 4; kc++) {
        // stage A chunk (transpose to [k][m], cvt tf32)
#pragma unroll
        for (int j = 0; j < 2; j++) {
            float4 v = __ldg(&aptr[kc * 8 + aq * 2 + j]);
            int k = aq * 8 + j * 4;
            xs[(k + 0) * MPAD + arow] = f2tf32(v.x);
            xs[(k + 1) * MPAD + arow] = f2tf32(v.y);
            xs[(k + 2) * MPAD + arow] = f2tf32(v.z);
            xs[(k + 3) * MPAD + arow] = f2tf32(v.w);
        }
        // stage B chunk ([k][n], cvt tf32)
        {
            const float4* bptr = (const float4*)&W[(size_t)(kc * 32 + bkk) * HD + bseg * 16];
#pragma unroll
            for (int q = 0; q < 4; q++) {
                float4 v = __ldg(&bptr[q]);
                uint4 u = make_uint4(f2tf32(v.x), f2tf32(v.y), f2tf32(v.z), f2tf32(v.w));
                *(uint4*)&ws[bkk * KPAD + bseg * 16 + q * 4] = u;
            }
        }
        __syncthreads();

#pragma unroll
        for (int ks = 0; ks < 4; ks++) {
            int k0 = ks * 8;
            uint32_t af[2][4], bf[4][2];
#pragma unroll
            for (int mf = 0; mf < 2; mf++) {
                int m0 = m_base + mf * 16;
                af[mf][0] = xs[(k0 + tg) * MPAD + m0 + g];
                af[mf][1] = xs[(k0 + tg) * MPAD + m0 + g + 8];
                af[mf][2] = xs[(k0 + tg + 4) * MPAD + m0 + g];
                af[mf][3] = xs[(k0 + tg + 4) * MPAD + m0 + g + 8];
            }
#pragma unroll
            for (int nf = 0; nf < 4; nf++) {
                int n0 = n_base + nf * 8;
                bf[nf][0] = ws[(k0 + tg) * KPAD + n0 + g];
                bf[nf][1] = ws[(k0 + tg + 4) * KPAD + n0 + g];
            }
#pragma unroll
            for (int mf = 0; mf < 2; mf++)
#pragma unroll
                for (int nf = 0; nf < 4; nf++)
                    mma_tf32(acc[mf][nf], af[mf], bf[nf]);
        }
        __syncthreads();
    }

    // ---- epilogue: direct half2 global stores + es/ed partial dots ----
    float ps[4] = {0.f, 0.f, 0.f, 0.f};   // rows: mf*2 + half
    float pd[4] = {0.f, 0.f, 0.f, 0.f};
#pragma unroll
    for (int nf = 0; nf < 4; nf++) {
        int c = n_base + nf * 8 + tg * 2;
        float a0 = __ldg(&as1[c]), a1 = __ldg(&as1[c + 1]);
        float d0 = __ldg(&ad1[c]), d1 = __ldg(&ad1[c + 1]);
#pragma unroll
        for (int mf = 0; mf < 2; mf++) {
            int row = blk0 + m_base + mf * 16 + g;
            ps[mf * 2 + 0] += acc[mf][nf][0] * a0 + acc[mf][nf][1] * a1;
            pd[mf * 2 + 0] += acc[mf][nf][0] * d0 + acc[mf][nf][1] * d1;
            ps[mf * 2 + 1] += acc[mf][nf][2] * a0 + acc[mf][nf][3] * a1;
            pd[mf * 2 + 1] += acc[mf][nf][2] * d0 + acc[mf][nf][3] * d1;
            if (row < N)
                *(uint32_t*)&g_xp1h[(size_t)row * HD + c] = f2h2(acc[mf][nf][0], acc[mf][nf][1]);
            if (row + 8 < N)
                *(uint32_t*)&g_xp1h[(size_t)(row + 8) * HD + c] = f2h2(acc[mf][nf][2], acc[mf][nf][3]);
        }
    }
    // quad reduce (over tg) and accumulate into smem
#pragma unroll
    for (int r = 0; r < 4; r++) {
#pragma unroll
        for (int off = 1; off < 4; off <<= 1) {
            ps[r] += __shfl_xor_sync(0xffffffffu, ps[r], off);
            pd[r] += __shfl_xor_sync(0xffffffffu, pd[r], off);
        }
    }
    if (tg == 0) {
#pragma unroll
        for (int r = 0; r < 4; r++) {
            int rl = m_base + (r >> 1) * 16 + (r & 1) * 8 + g;
            atomicAdd(&es_s[rl], ps[r]);
            atomicAdd(&ed_s[rl], pd[r]);
        }
    }
    __syncthreads();
    if (tid < 64) {
        int row = blk0 + tid;
        if (row < N) {
            g_es[row] = es_s[tid];
            g_ed[row] = ed_s[tid];
        }
    }
}

// =======================================================================
// Layer-1 fused node kernel (warp per node), single pass, 4-way batched
// fp16 row gathers. Fused xp2 = relu(out1 + b1) . W2.
// =======================================================================
__global__ void __launch_bounds__(256) k_node1(
    const float* __restrict__ b1, const float* __restrict__ W2, int N)
{
    if (blockIdx.x == 0 && threadIdx.x == 0) g_cnt = 0;   // reset for next run
    int lane = threadIdx.x & 31;
    int node = blockIdx.x * 8 + (threadIdx.x >> 5);
    if (node >= N) return;

    int r0 = __ldg(&g_rowptr[node]);
    int r1 = __ldg(&g_rowptr[node + 1]);
    float edv = g_ed[node];
    float sw = __expf(lrelu(g_es[node] + edv));

    float4 sv = gather_h4(node, lane);

    float4 accv = make_float4(0.f, 0.f, 0.f, 0.f);
    float den_part = 0.f;
    for (int base = r0; base < r1; base += 32) {
        int e = base + lane;
        float wgt = 0.f; int src = 0;
        if (e < r1) {
            src = g_csr[e];
            wgt = __expf(lrelu(__ldg(&g_es[src]) + edv));
            den_part += wgt;
        }
        int cnt = min(32, r1 - base);
        int j = 0;
        for (; j + 4 <= cnt; j += 4) {
            float w0 = __shfl_sync(0xffffffffu, wgt, j);
            float w1 = __shfl_sync(0xffffffffu, wgt, j + 1);
            float w2 = __shfl_sync(0xffffffffu, wgt, j + 2);
            float w3 = __shfl_sync(0xffffffffu, wgt, j + 3);
            int s0 = __shfl_sync(0xffffffffu, src, j);
            int s1 = __shfl_sync(0xffffffffu, src, j + 1);
            int s2 = __shfl_sync(0xffffffffu, src, j + 2);
            int s3 = __shfl_sync(0xffffffffu, src, j + 3);
            float4 v0 = gather_h4(s0, lane);
            float4 v1 = gather_h4(s1, lane);
            float4 v2 = gather_h4(s2, lane);
            float4 v3 = gather_h4(s3, lane);
            accv.x += w0 * v0.x + w1 * v1.x + w2 * v2.x + w3 * v3.x;
            accv.y += w0 * v0.y + w1 * v1.y + w2 * v2.y + w3 * v3.y;
            accv.z += w0 * v0.z + w1 * v1.z + w2 * v2.z + w3 * v3.z;
            accv.w += w0 * v0.w + w1 * v1.w + w2 * v2.w + w3 * v3.w;
        }
        for (; j < cnt; j++) {
            float wj = __shfl_sync(0xffffffffu, wgt, j);
            int   sj = __shfl_sync(0xffffffffu, src, j);
            float4 v = gather_h4(sj, lane);
            accv.x += wj * v.x; accv.y += wj * v.y;
            accv.z += wj * v.z; accv.w += wj * v.w;
        }
    }
#pragma unroll
    for (int off = 16; off; off >>= 1)
        den_part += __shfl_xor_sync(0xffffffffu, den_part, off);
    float inv = __frcp_rn(den_part + sw);

    accv.x = (accv.x + sw * sv.x) * inv;
    accv.y = (accv.y + sw * sv.y) * inv;
    accv.z = (accv.z + sw * sv.z) * inv;
    accv.w = (accv.w + sw * sv.w) * inv;

    float4 bb = __ldg((const float4*)&b1[lane * 4]);
    float4 ww = __ldg((const float4*)&W2[lane * 4]);
    float s = fmaxf(accv.x + bb.x, 0.f) * ww.x + fmaxf(accv.y + bb.y, 0.f) * ww.y +
              fmaxf(accv.z + bb.z, 0.f) * ww.z + fmaxf(accv.w + bb.w, 0.f) * ww.w;
#pragma unroll
    for (int off = 16; off; off >>= 1) s += __shfl_xor_sync(0xffffffffu, s, off);
    if (lane == 0) g_xp2[node] = s;
}

// =======================================================================
// Layer-2 fused node kernel (thread per node, OUT=1), single pass.
// =======================================================================
__global__ void k_node2(const float* __restrict__ as2, const float* __restrict__ ad2,
                        const float* __restrict__ b2, float* __restrict__ out, int N)
{
    int i = blockIdx.x * blockDim.x + threadIdx.x;
    if (i >= N) return;
    float a = __ldg(&as2[0]), b = __ldg(&ad2[0]);
    float xi = g_xp2[i];
    int r0 = g_rowptr[i], r1 = g_rowptr[i + 1];
    float xib = xi * b;
    float sw = __expf(lrelu(xi * a + xib));
    float den = sw, num = sw * xi;
    for (int e = r0; e < r1; e++) {
        float xs = __ldg(&g_xp2[g_csr[e]]);
        float w = __expf(lrelu(xs * a + xib));
        den += w;
        num += w * xs;
    }
    out[i] = num / den + __ldg(&b2[0]);
}

// ---------------- launch ----------------
extern "C" void kernel_launch(void* const* d_in, const int* in_sizes, int n_in,
                              void* d_out, int out_size) {
    const int*   h    = (const int*)d_in[0];
    const int*   ei   = (const int*)d_in[1];
    const int*   nt   = (const int*)d_in[2];
    const float* emb  = (const float*)d_in[3];
    const float* W1   = (const float*)d_in[4];
    const float* as1  = (const float*)d_in[5];
    const float* ad1  = (const float*)d_in[6];
    const float* b1   = (const float*)d_in[7];
    const float* W2   = (const float*)d_in[8];
    const float* as2  = (const float*)d_in[9];
    const float* ad2  = (const float*)d_in[10];
    const float* b2   = (const float*)d_in[11];
    float* out = (float*)d_out;

    int N = in_sizes[0];
    int E = in_sizes[1] / 2;
    int nb = (N + 255) / 256;
    int nscan = (N + SCAN_B - 1) / SCAN_B;

    static cudaStream_t s2 = nullptr;
    static cudaEvent_t evFork = nullptr, evJoin = nullptr;
    if (!s2) {
        cudaStreamCreateWithFlags(&s2, cudaStreamNonBlocking);
        cudaEventCreateWithFlags(&evFork, cudaEventDisableTiming);
        cudaEventCreateWithFlags(&evJoin, cudaEventDisableTiming);
    }

    // fork event first: GEMM (submitted 4th for ncu targeting) still runs
    // concurrently with the CSR chain in the captured graph.
    cudaEventRecord(evFork, 0);
    cudaStreamWaitEvent(s2, evFork, 0);

    // CSR build part 1 (main stream) — launches 1..3
    k_deg<<<1024, 256>>>(ei, nt, E);
    k_scanA<<<nscan, SCAN_B>>>(N);
    k_scanC<<<nb, 256>>>(N);

    // GEMM on s2 — launch 4 (lands in the ncu -s 5 -c 1 window)
    k_gemm1_tc<<<(N + 63) / 64, 256, 0, s2>>>(h, emb, W1, as1, ad1, N);
    cudaEventRecord(evJoin, s2);

    // CSR build part 2 — launch 5
    k_scatter<<<1024, 256>>>();

    cudaStreamWaitEvent(0, evJoin, 0);

    k_node1<<<(N + 7) / 8, 256>>>(b1, W2, N);
    k_node2<<<nb, 256>>>(as2, ad2, b2, out, N);
}

// round 15
// speedup vs baseline: 1.1159x; 1.1159x over previous
#include <cuda_runtime.h>
#include <cuda_fp16.h>
#include <cstdint>

#define MAXN 100000
#define MAXE 1600000
#define HD 128
#define SLOPE 0.2f
#define SCAN_B 1024

// ---------------- scratch (device globals) ----------------
__device__ __half g_xp1h[(size_t)MAXN * HD];   // layer1 x@W1 in fp16
__device__ float g_es[MAXN];
__device__ float g_ed[MAXN];
__device__ float g_xp2[MAXN];
__device__ int   g_cs[MAXE];
__device__ int   g_cd[MAXE];
__device__ int   g_csr[MAXE];
__device__ int   g_deg[MAXN];      // re-zeroed each run by k_scanC
__device__ int   g_cur[MAXN];
__device__ int   g_scan[MAXN];
__device__ int   g_rowptr[MAXN + 1];
__device__ int   g_bsum[128];
__device__ int   g_boff[128];
__device__ int   g_cnt;            // re-zeroed each run by k_node1
__device__ unsigned g_tick;        // reset by scanA's last block

// ---------------- helpers ----------------
__device__ __forceinline__ float lrelu(float x) { return x > 0.f ? x : SLOPE * x; }

__device__ __forceinline__ uint32_t f2tf32(float f) {
    uint32_t r; asm("cvt.rna.tf32.f32 %0, %1;" : "=r"(r) : "f"(f)); return r;
}

__device__ __forceinline__ uint32_t f2h2(float a, float b) {
    __half2 h = __floats2half2_rn(a, b);
    return *(uint32_t*)&h;
}

__device__ __forceinline__ void mma_tf32(float* c, const uint32_t* a, const uint32_t* b) {
    asm volatile("mma.sync.aligned.m16n8k8.row.col.f32.tf32.tf32.f32 "
                 "{%0,%1,%2,%3}, {%4,%5,%6,%7}, {%8,%9}, {%0,%1,%2,%3};"
                 : "+f"(c[0]), "+f"(c[1]), "+f"(c[2]), "+f"(c[3])
                 : "r"(a[0]), "r"(a[1]), "r"(a[2]), "r"(a[3]), "r"(b[0]), "r"(b[1]));
}

// fp16 row gather: 4 dims per lane as uint2 -> float4 (fp32 math)
__device__ __forceinline__ float4 gather_h4(int row, int lane) {
    uint2 u = __ldg((const uint2*)&g_xp1h[(size_t)row * HD] + lane);
    float2 lo = __half22float2(*(__half2*)&u.x);
    float2 hi = __half22float2(*(__half2*)&u.y);
    return make_float4(lo.x, lo.y, hi.x, hi.y);
}

// ---------------- compact + degree ----------------
__global__ void k_deg(const int* __restrict__ ei, const int* __restrict__ nt, int E) {
    int Er = (E + 31) & ~31;
    int lane = threadIdx.x & 31;
    int stride = gridDim.x * blockDim.x;
    for (int i = blockIdx.x * blockDim.x + threadIdx.x; i < Er; i += stride) {
        int s = 0, d = 0;
        bool act = false;
        if (i < E) {
            s = ei[i];
            d = ei[E + i];
            act = (__ldg(&nt[s]) == 0) && (__ldg(&nt[d]) == 0);
        }
        unsigned ball = __ballot_sync(0xffffffffu, act);
        if (ball) {
            int leader = __ffs(ball) - 1;
            int base = 0;
            if (lane == leader) base = atomicAdd(&g_cnt, __popc(ball));
            base = __shfl_sync(0xffffffffu, base, leader);
            if (act) {
                int off = __popc(ball & ((1u << lane) - 1u));
                g_cs[base + off] = s;
                g_cd[base + off] = d;
                atomicAdd(&g_deg[d], 1);
            }
        }
    }
}

// ---------------- scan ----------------
__global__ void __launch_bounds__(SCAN_B) k_scanA(int N) {
    __shared__ int wsum[32];
    __shared__ bool isLast;
    int tid = threadIdx.x;
    int lane = tid & 31;
    int wid = tid >> 5;
    int i = blockIdx.x * SCAN_B + tid;
    int v = (i < N) ? g_deg[i] : 0;

#pragma unroll
    for (int off = 1; off < 32; off <<= 1) {
        int t = __shfl_up_sync(0xffffffffu, v, off);
        if (lane >= off) v += t;
    }
    if (lane == 31) wsum[wid] = v;
    __syncthreads();
    if (wid == 0) {
        int w = wsum[lane];
#pragma unroll
        for (int off = 1; off < 32; off <<= 1) {
            int t = __shfl_up_sync(0xffffffffu, w, off);
            if (lane >= off) w += t;
        }
        wsum[lane] = w;
    }
    __syncthreads();
    if (wid) v += wsum[wid - 1];

    if (i < N) g_scan[i] = v;
    if (tid == SCAN_B - 1) g_bsum[blockIdx.x] = v;

    __threadfence();
    __syncthreads();
    if (tid == 0) {
        unsigned t = atomicAdd(&g_tick, 1u);
        isLast = (t == gridDim.x - 1);
    }
    __syncthreads();
    if (isLast && wid == 0) {
        int nb = gridDim.x;
        int total = 0;
        for (int c = 0; c * 32 < nb; c++) {
            int idx = c * 32 + lane;
            int x = (idx < nb) ? g_bsum[idx] : 0;
#pragma unroll
            for (int off = 1; off < 32; off <<= 1) {
                int t2 = __shfl_up_sync(0xffffffffu, x, off);
                if (lane >= off) x += t2;
            }
            if (idx < nb) g_boff[idx] = x + total;
            total += __shfl_sync(0xffffffffu, x, 31);
        }
        if (lane == 0) g_tick = 0;
        __threadfence();
    }
}

__global__ void k_scanC(int N) {
    int i = blockIdx.x * blockDim.x + threadIdx.x;
    if (i < N) {
        int b = i >> 10;
        int off = b ? g_boff[b - 1] : 0;
        int incl = off + g_scan[i];
        g_rowptr[i + 1] = incl;
        g_cur[i] = incl - g_deg[i];
        g_deg[i] = 0;
        if (i == 0) g_rowptr[0] = 0;
    }
}

__global__ void k_scatter() {
    int cnt = g_cnt;
    int st = gridDim.x * blockDim.x;
    for (int i = blockIdx.x * blockDim.x + threadIdx.x; i < cnt; i += st) {
        int s = g_cs[i], d = g_cd[i];
        int pos = atomicAdd(&g_cur[d], 1);
        g_csr[pos] = s;
    }
}

// =======================================================================
// GEMM1: R13 mainloop (128x128 tile, 2 CTA/SM) + direct-store epilogue
// (no smem round-trip, no extra syncs). es/ed via quad-shuffle + smem
// atomic merge across the 2 warps sharing each row range.
// =======================================================================
static constexpr int KPAD = 136;

__global__ void __launch_bounds__(256, 2)
k_gemm1_tc(const int* __restrict__ hidx, const float* __restrict__ emb,
           const float* __restrict__ W,
           const float* __restrict__ as1, const float* __restrict__ ad1, int N)
{
    __shared__ uint32_t xs[32 * KPAD];   // A chunk [k][m]
    __shared__ uint32_t ws[32 * KPAD];   // B chunk [k][n]
    __shared__ float es_s[128], ed_s[128];

    int tid  = threadIdx.x;
    int lane = tid & 31;
    int wid  = tid >> 5;
    int g    = lane >> 2;
    int tg   = lane & 3;
    int m_base = (wid & 3) * 32;
    int n_base = (wid >> 2) * 64;
    int blk0 = blockIdx.x * 128;

    if (tid < 128) { es_s[tid] = 0.f; ed_s[tid] = 0.f; }

    float acc[2][8][4];
#pragma unroll
    for (int mf = 0; mf < 2; mf++)
#pragma unroll
        for (int nf = 0; nf < 8; nf++)
#pragma unroll
            for (int q = 0; q < 4; q++) acc[mf][nf][q] = 0.f;

    int arow = tid >> 1;
    int ahalf = tid & 1;
    int grow = blk0 + arow;
    int hrow = (grow < N) ? __ldg(&hidx[grow]) : 0;
    const float4* aptr = (const float4*)&emb[(size_t)hrow * HD];

    int bkk = tid >> 3;
    int bseg = tid & 7;

    for (int kc = 0; kc < 4; kc++) {
#pragma unroll
        for (int q = 0; q < 4; q++) {
            float4 v = __ldg(&aptr[kc * 8 + ahalf * 4 + q]);
            int k = ahalf * 16 + q * 4;
            xs[(k + 0) * KPAD + arow] = f2tf32(v.x);
            xs[(k + 1) * KPAD + arow] = f2tf32(v.y);
            xs[(k + 2) * KPAD + arow] = f2tf32(v.z);
            xs[(k + 3) * KPAD + arow] = f2tf32(v.w);
        }
        {
            const float4* bptr = (const float4*)&W[(size_t)(kc * 32 + bkk) * HD + bseg * 16];
#pragma unroll
            for (int q = 0; q < 4; q++) {
                float4 v = __ldg(&bptr[q]);
                uint4 u = make_uint4(f2tf32(v.x), f2tf32(v.y), f2tf32(v.z), f2tf32(v.w));
                *(uint4*)&ws[bkk * KPAD + bseg * 16 + q * 4] = u;
            }
        }
        __syncthreads();

#pragma unroll
        for (int ks = 0; ks < 4; ks++) {
            int k0 = ks * 8;
            uint32_t af[2][4], bf[8][2];
#pragma unroll
            for (int mf = 0; mf < 2; mf++) {
                int m0 = m_base + mf * 16;
                af[mf][0] = xs[(k0 + tg) * KPAD + m0 + g];
                af[mf][1] = xs[(k0 + tg) * KPAD + m0 + g + 8];
                af[mf][2] = xs[(k0 + tg + 4) * KPAD + m0 + g];
                af[mf][3] = xs[(k0 + tg + 4) * KPAD + m0 + g + 8];
            }
#pragma unroll
            for (int nf = 0; nf < 8; nf++) {
                int n0 = n_base + nf * 8;
                bf[nf][0] = ws[(k0 + tg) * KPAD + n0 + g];
                bf[nf][1] = ws[(k0 + tg + 4) * KPAD + n0 + g];
            }
#pragma unroll
            for (int mf = 0; mf < 2; mf++)
#pragma unroll
                for (int nf = 0; nf < 8; nf++)
                    mma_tf32(acc[mf][nf], af[mf], bf[nf]);
        }
        __syncthreads();
    }

    // ---- epilogue: direct half2 stores + in-register es/ed dots ----
    float ps[4] = {0.f, 0.f, 0.f, 0.f};   // r = mf*2 + half
    float pd[4] = {0.f, 0.f, 0.f, 0.f};
#pragma unroll
    for (int nf = 0; nf < 8; nf++) {
        int c = n_base + nf * 8 + tg * 2;
        float a0 = __ldg(&as1[c]), a1 = __ldg(&as1[c + 1]);
        float d0 = __ldg(&ad1[c]), d1 = __ldg(&ad1[c + 1]);
#pragma unroll
        for (int mf = 0; mf < 2; mf++) {
            int row = blk0 + m_base + mf * 16 + g;
            ps[mf * 2 + 0] += acc[mf][nf][0] * a0 + acc[mf][nf][1] * a1;
            pd[mf * 2 + 0] += acc[mf][nf][0] * d0 + acc[mf][nf][1] * d1;
            ps[mf * 2 + 1] += acc[mf][nf][2] * a0 + acc[mf][nf][3] * a1;
            pd[mf * 2 + 1] += acc[mf][nf][2] * d0 + acc[mf][nf][3] * d1;
            if (row < N)
                *(uint32_t*)&g_xp1h[(size_t)row * HD + c] = f2h2(acc[mf][nf][0], acc[mf][nf][1]);
            if (row + 8 < N)
                *(uint32_t*)&g_xp1h[(size_t)(row + 8) * HD + c] = f2h2(acc[mf][nf][2], acc[mf][nf][3]);
        }
    }
#pragma unroll
    for (int r = 0; r < 4; r++) {
#pragma unroll
        for (int off = 1; off < 4; off <<= 1) {
            ps[r] += __shfl_xor_sync(0xffffffffu, ps[r], off);
            pd[r] += __shfl_xor_sync(0xffffffffu, pd[r], off);
        }
    }
    if (tg == 0) {
#pragma unroll
        for (int r = 0; r < 4; r++) {
            int rl = m_base + (r >> 1) * 16 + (r & 1) * 8 + g;
            atomicAdd(&es_s[rl], ps[r]);
            atomicAdd(&ed_s[rl], pd[r]);
        }
    }
    __syncthreads();
    if (tid < 128) {
        int row = blk0 + tid;
        if (row < N) {
            g_es[row] = es_s[tid];
            g_ed[row] = ed_s[tid];
        }
    }
}

// =======================================================================
// Layer-1 fused node kernel (warp per node), single pass, 4-way batched
// fp16 row gathers. Fused xp2 = relu(out1 + b1) . W2.
// =======================================================================
__global__ void __launch_bounds__(256) k_node1(
    const float* __restrict__ b1, const float* __restrict__ W2, int N)
{
    if (blockIdx.x == 0 && threadIdx.x == 0) g_cnt = 0;   // reset for next run
    int lane = threadIdx.x & 31;
    int node = blockIdx.x * 8 + (threadIdx.x >> 5);
    if (node >= N) return;

    int r0 = __ldg(&g_rowptr[node]);
    int r1 = __ldg(&g_rowptr[node + 1]);
    float edv = g_ed[node];
    float sw = __expf(lrelu(g_es[node] + edv));

    float4 sv = gather_h4(node, lane);

    float4 accv = make_float4(0.f, 0.f, 0.f, 0.f);
    float den_part = 0.f;
    for (int base = r0; base < r1; base += 32) {
        int e = base + lane;
        float wgt = 0.f; int src = 0;
        if (e < r1) {
            src = g_csr[e];
            wgt = __expf(lrelu(__ldg(&g_es[src]) + edv));
            den_part += wgt;
        }
        int cnt = min(32, r1 - base);
        int j = 0;
        for (; j + 4 <= cnt; j += 4) {
            float w0 = __shfl_sync(0xffffffffu, wgt, j);
            float w1 = __shfl_sync(0xffffffffu, wgt, j + 1);
            float w2 = __shfl_sync(0xffffffffu, wgt, j + 2);
            float w3 = __shfl_sync(0xffffffffu, wgt, j + 3);
            int s0 = __shfl_sync(0xffffffffu, src, j);
            int s1 = __shfl_sync(0xffffffffu, src, j + 1);
            int s2 = __shfl_sync(0xffffffffu, src, j + 2);
            int s3 = __shfl_sync(0xffffffffu, src, j + 3);
            float4 v0 = gather_h4(s0, lane);
            float4 v1 = gather_h4(s1, lane);
            float4 v2 = gather_h4(s2, lane);
            float4 v3 = gather_h4(s3, lane);
            accv.x += w0 * v0.x + w1 * v1.x + w2 * v2.x + w3 * v3.x;
            accv.y += w0 * v0.y + w1 * v1.y + w2 * v2.y + w3 * v3.y;
            accv.z += w0 * v0.z + w1 * v1.z + w2 * v2.z + w3 * v3.z;
            accv.w += w0 * v0.w + w1 * v1.w + w2 * v2.w + w3 * v3.w;
        }
        for (; j < cnt; j++) {
            float wj = __shfl_sync(0xffffffffu, wgt, j);
            int   sj = __shfl_sync(0xffffffffu, src, j);
            float4 v = gather_h4(sj, lane);
            accv.x += wj * v.x; accv.y += wj * v.y;
            accv.z += wj * v.z; accv.w += wj * v.w;
        }
    }
#pragma unroll
    for (int off = 16; off; off >>= 1)
        den_part += __shfl_xor_sync(0xffffffffu, den_part, off);
    float inv = __frcp_rn(den_part + sw);

    accv.x = (accv.x + sw * sv.x) * inv;
    accv.y = (accv.y + sw * sv.y) * inv;
    accv.z = (accv.z + sw * sv.z) * inv;
    accv.w = (accv.w + sw * sv.w) * inv;

    float4 bb = __ldg((const float4*)&b1[lane * 4]);
    float4 ww = __ldg((const float4*)&W2[lane * 4]);
    float s = fmaxf(accv.x + bb.x, 0.f) * ww.x + fmaxf(accv.y + bb.y, 0.f) * ww.y +
              fmaxf(accv.z + bb.z, 0.f) * ww.z + fmaxf(accv.w + bb.w, 0.f) * ww.w;
#pragma unroll
    for (int off = 16; off; off >>= 1) s += __shfl_xor_sync(0xffffffffu, s, off);
    if (lane == 0) g_xp2[node] = s;
}

// =======================================================================
// Layer-2 fused node kernel (thread per node, OUT=1), single pass.
// =======================================================================
__global__ void k_node2(const float* __restrict__ as2, const float* __restrict__ ad2,
                        const float* __restrict__ b2, float* __restrict__ out, int N)
{
    int i = blockIdx.x * blockDim.x + threadIdx.x;
    if (i >= N) return;
    float a = __ldg(&as2[0]), b = __ldg(&ad2[0]);
    float xi = g_xp2[i];
    int r0 = g_rowptr[i], r1 = g_rowptr[i + 1];
    float xib = xi * b;
    float sw = __expf(lrelu(xi * a + xib));
    float den = sw, num = sw * xi;
    for (int e = r0; e < r1; e++) {
        float xs = __ldg(&g_xp2[g_csr[e]]);
        float w = __expf(lrelu(xs * a + xib));
        den += w;
        num += w * xs;
    }
    out[i] = num / den + __ldg(&b2[0]);
}

// ---------------- launch ----------------
extern "C" void kernel_launch(void* const* d_in, const int* in_sizes, int n_in,
                              void* d_out, int out_size) {
    const int*   h    = (const int*)d_in[0];
    const int*   ei   = (const int*)d_in[1];
    const int*   nt   = (const int*)d_in[2];
    const float* emb  = (const float*)d_in[3];
    const float* W1   = (const float*)d_in[4];
    const float* as1  = (const float*)d_in[5];
    const float* ad1  = (const float*)d_in[6];
    const float* b1   = (const float*)d_in[7];
    const float* W2   = (const float*)d_in[8];
    const float* as2  = (const float*)d_in[9];
    const float* ad2  = (const float*)d_in[10];
    const float* b2   = (const float*)d_in[11];
    float* out = (float*)d_out;

    int N = in_sizes[0];
    int E = in_sizes[1] / 2;
    int nb = (N + 255) / 256;
    int nscan = (N + SCAN_B - 1) / SCAN_B;

    static cudaStream_t s2 = nullptr;
    static cudaEvent_t evFork = nullptr, evJoin = nullptr;
    if (!s2) {
        cudaStreamCreateWithFlags(&s2, cudaStreamNonBlocking);
        cudaEventCreateWithFlags(&evFork, cudaEventDisableTiming);
        cudaEventCreateWithFlags(&evJoin, cudaEventDisableTiming);
    }

    // fork event first: GEMM (submitted 4th for ncu targeting) still runs
    // concurrently with the CSR chain in the captured graph.
    cudaEventRecord(evFork, 0);
    cudaStreamWaitEvent(s2, evFork, 0);

    // CSR build part 1 (main stream) — launches 1..3
    k_deg<<<1024, 256>>>(ei, nt, E);
    k_scanA<<<nscan, SCAN_B>>>(N);
    k_scanC<<<nb, 256>>>(N);

    // GEMM on s2 — launch 4 (lands in the ncu -s 5 -c 1 window)
    k_gemm1_tc<<<(N + 127) / 128, 256, 0, s2>>>(h, emb, W1, as1, ad1, N);
    cudaEventRecord(evJoin, s2);

    // CSR build part 2 — launch 5
    k_scatter<<<1024, 256>>>();

    cudaStreamWaitEvent(0, evJoin, 0);

    k_node1<<<(N + 7) / 8, 256>>>(b1, W2, N);
    k_node2<<<nb, 256>>>(as2, ad2, b2, out, N);
}

// round 17
// speedup vs baseline: 1.1397x; 1.0213x over previous
#include <cuda_runtime.h>
#include <cuda_fp16.h>
#include <cstdint>

#define MAXN 100000
#define MAXE 1600000
#define HD 128
#define SLOPE 0.2f
#define SCAN_B 1024

// ---------------- scratch (device globals) ----------------
__device__ __half g_xp1h[(size_t)MAXN * HD];   // layer1 x@W1 in fp16
__device__ float g_es[MAXN];
__device__ float g_ed[MAXN];
__device__ float g_xp2[MAXN];
__device__ int   g_cs[MAXE];
__device__ int   g_cd[MAXE];
__device__ int   g_csr[MAXE];
__device__ int   g_deg[MAXN];      // re-zeroed each run by k_scanC
__device__ int   g_cur[MAXN];
__device__ int   g_scan[MAXN];
__device__ int   g_rowptr[MAXN + 1];
__device__ int   g_bsum[128];
__device__ int   g_boff[128];
__device__ int   g_cnt;            // re-zeroed each run by k_node1
__device__ unsigned g_tick;        // reset by scanA's last block

// ---------------- helpers ----------------
__device__ __forceinline__ float lrelu(float x) { return x > 0.f ? x : SLOPE * x; }

__device__ __forceinline__ uint32_t f2tf32(float f) {
    uint32_t r; asm("cvt.rna.tf32.f32 %0, %1;" : "=r"(r) : "f"(f)); return r;
}

__device__ __forceinline__ uint32_t f2h2(float a, float b) {
    __half2 h = __floats2half2_rn(a, b);
    return *(uint32_t*)&h;
}

__device__ __forceinline__ void mma_tf32(float* c, const uint32_t* a, const uint32_t* b) {
    asm volatile("mma.sync.aligned.m16n8k8.row.col.f32.tf32.tf32.f32 "
                 "{%0,%1,%2,%3}, {%4,%5,%6,%7}, {%8,%9}, {%0,%1,%2,%3};"
                 : "+f"(c[0]), "+f"(c[1]), "+f"(c[2]), "+f"(c[3])
                 : "r"(a[0]), "r"(a[1]), "r"(a[2]), "r"(a[3]), "r"(b[0]), "r"(b[1]));
}

// ---------------- compact + degree ----------------
__global__ void k_deg(const int* __restrict__ ei, const int* __restrict__ nt, int E) {
    int Er = (E + 31) & ~31;
    int lane = threadIdx.x & 31;
    int stride = gridDim.x * blockDim.x;
    for (int i = blockIdx.x * blockDim.x + threadIdx.x; i < Er; i += stride) {
        int s = 0, d = 0;
        bool act = false;
        if (i < E) {
            s = ei[i];
            d = ei[E + i];
            act = (__ldg(&nt[s]) == 0) && (__ldg(&nt[d]) == 0);
        }
        unsigned ball = __ballot_sync(0xffffffffu, act);
        if (ball) {
            int leader = __ffs(ball) - 1;
            int base = 0;
            if (lane == leader) base = atomicAdd(&g_cnt, __popc(ball));
            base = __shfl_sync(0xffffffffu, base, leader);
            if (act) {
                int off = __popc(ball & ((1u << lane) - 1u));
                g_cs[base + off] = s;
                g_cd[base + off] = d;
                atomicAdd(&g_deg[d], 1);
            }
        }
    }
}

// ---------------- scan ----------------
__global__ void __launch_bounds__(SCAN_B) k_scanA(int N) {
    __shared__ int wsum[32];
    __shared__ bool isLast;
    int tid = threadIdx.x;
    int lane = tid & 31;
    int wid = tid >> 5;
    int i = blockIdx.x * SCAN_B + tid;
    int v = (i < N) ? g_deg[i] : 0;

#pragma unroll
    for (int off = 1; off < 32; off <<= 1) {
        int t = __shfl_up_sync(0xffffffffu, v, off);
        if (lane >= off) v += t;
    }
    if (lane == 31) wsum[wid] = v;
    __syncthreads();
    if (wid == 0) {
        int w = wsum[lane];
#pragma unroll
        for (int off = 1; off < 32; off <<= 1) {
            int t = __shfl_up_sync(0xffffffffu, w, off);
            if (lane >= off) w += t;
        }
        wsum[lane] = w;
    }
    __syncthreads();
    if (wid) v += wsum[wid - 1];

    if (i < N) g_scan[i] = v;
    if (tid == SCAN_B - 1) g_bsum[blockIdx.x] = v;

    __threadfence();
    __syncthreads();
    if (tid == 0) {
        unsigned t = atomicAdd(&g_tick, 1u);
        isLast = (t == gridDim.x - 1);
    }
    __syncthreads();
    if (isLast && wid == 0) {
        int nb = gridDim.x;
        int total = 0;
        for (int c = 0; c * 32 < nb; c++) {
            int idx = c * 32 + lane;
            int x = (idx < nb) ? g_bsum[idx] : 0;
#pragma unroll
            for (int off = 1; off < 32; off <<= 1) {
                int t2 = __shfl_up_sync(0xffffffffu, x, off);
                if (lane >= off) x += t2;
            }
            if (idx < nb) g_boff[idx] = x + total;
            total += __shfl_sync(0xffffffffu, x, 31);
        }
        if (lane == 0) g_tick = 0;
        __threadfence();
    }
}

__global__ void k_scanC(int N) {
    int i = blockIdx.x * blockDim.x + threadIdx.x;
    if (i < N) {
        int b = i >> 10;
        int off = b ? g_boff[b - 1] : 0;
        int incl = off + g_scan[i];
        g_rowptr[i + 1] = incl;
        g_cur[i] = incl - g_deg[i];
        g_deg[i] = 0;
        if (i == 0) g_rowptr[0] = 0;
    }
}

__global__ void k_scatter() {
    int cnt = g_cnt;
    int st = gridDim.x * blockDim.x;
    for (int i = blockIdx.x * blockDim.x + threadIdx.x; i < cnt; i += st) {
        int s = g_cs[i], d = g_cd[i];
        int pos = atomicAdd(&g_cur[d], 1);
        g_csr[pos] = s;
    }
}

// =======================================================================
// GEMM1 (R15-proven): 128x128 tile, 2 CTA/SM, direct-store epilogue.
// =======================================================================
static constexpr int KPAD = 136;

__global__ void __launch_bounds__(256, 2)
k_gemm1_tc(const int* __restrict__ hidx, const float* __restrict__ emb,
           const float* __restrict__ W,
           const float* __restrict__ as1, const float* __restrict__ ad1, int N)
{
    __shared__ uint32_t xs[32 * KPAD];   // A chunk [k][m]
    __shared__ uint32_t ws[32 * KPAD];   // B chunk [k][n]
    __shared__ float es_s[128], ed_s[128];

    int tid  = threadIdx.x;
    int lane = tid & 31;
    int wid  = tid >> 5;
    int g    = lane >> 2;
    int tg   = lane & 3;
    int m_base = (wid & 3) * 32;
    int n_base = (wid >> 2) * 64;
    int blk0 = blockIdx.x * 128;

    if (tid < 128) { es_s[tid] = 0.f; ed_s[tid] = 0.f; }

    float acc[2][8][4];
#pragma unroll
    for (int mf = 0; mf < 2; mf++)
#pragma unroll
        for (int nf = 0; nf < 8; nf++)
#pragma unroll
            for (int q = 0; q < 4; q++) acc[mf][nf][q] = 0.f;

    int arow = tid >> 1;
    int ahalf = tid & 1;
    int grow = blk0 + arow;
    int hrow = (grow < N) ? __ldg(&hidx[grow]) : 0;
    const float4* aptr = (const float4*)&emb[(size_t)hrow * HD];

    int bkk = tid >> 3;
    int bseg = tid & 7;

    for (int kc = 0; kc < 4; kc++) {
#pragma unroll
        for (int q = 0; q < 4; q++) {
            float4 v = __ldg(&aptr[kc * 8 + ahalf * 4 + q]);
            int k = ahalf * 16 + q * 4;
            xs[(k + 0) * KPAD + arow] = f2tf32(v.x);
            xs[(k + 1) * KPAD + arow] = f2tf32(v.y);
            xs[(k + 2) * KPAD + arow] = f2tf32(v.z);
            xs[(k + 3) * KPAD + arow] = f2tf32(v.w);
        }
        {
            const float4* bptr = (const float4*)&W[(size_t)(kc * 32 + bkk) * HD + bseg * 16];
#pragma unroll
            for (int q = 0; q < 4; q++) {
                float4 v = __ldg(&bptr[q]);
                uint4 u = make_uint4(f2tf32(v.x), f2tf32(v.y), f2tf32(v.z), f2tf32(v.w));
                *(uint4*)&ws[bkk * KPAD + bseg * 16 + q * 4] = u;
            }
        }
        __syncthreads();

#pragma unroll
        for (int ks = 0; ks < 4; ks++) {
            int k0 = ks * 8;
            uint32_t af[2][4], bf[8][2];
#pragma unroll
            for (int mf = 0; mf < 2; mf++) {
                int m0 = m_base + mf * 16;
                af[mf][0] = xs[(k0 + tg) * KPAD + m0 + g];
                af[mf][1] = xs[(k0 + tg) * KPAD + m0 + g + 8];
                af[mf][2] = xs[(k0 + tg + 4) * KPAD + m0 + g];
                af[mf][3] = xs[(k0 + tg + 4) * KPAD + m0 + g + 8];
            }
#pragma unroll
            for (int nf = 0; nf < 8; nf++) {
                int n0 = n_base + nf * 8;
                bf[nf][0] = ws[(k0 + tg) * KPAD + n0 + g];
                bf[nf][1] = ws[(k0 + tg + 4) * KPAD + n0 + g];
            }
#pragma unroll
            for (int mf = 0; mf < 2; mf++)
#pragma unroll
                for (int nf = 0; nf < 8; nf++)
                    mma_tf32(acc[mf][nf], af[mf], bf[nf]);
        }
        __syncthreads();
    }

    // ---- epilogue: direct half2 stores + in-register es/ed dots ----
    float ps[4] = {0.f, 0.f, 0.f, 0.f};
    float pd[4] = {0.f, 0.f, 0.f, 0.f};
#pragma unroll
    for (int nf = 0; nf < 8; nf++) {
        int c = n_base + nf * 8 + tg * 2;
        float a0 = __ldg(&as1[c]), a1 = __ldg(&as1[c + 1]);
        float d0 = __ldg(&ad1[c]), d1 = __ldg(&ad1[c + 1]);
#pragma unroll
        for (int mf = 0; mf < 2; mf++) {
            int row = blk0 + m_base + mf * 16 + g;
            ps[mf * 2 + 0] += acc[mf][nf][0] * a0 + acc[mf][nf][1] * a1;
            pd[mf * 2 + 0] += acc[mf][nf][0] * d0 + acc[mf][nf][1] * d1;
            ps[mf * 2 + 1] += acc[mf][nf][2] * a0 + acc[mf][nf][3] * a1;
            pd[mf * 2 + 1] += acc[mf][nf][2] * d0 + acc[mf][nf][3] * d1;
            if (row < N)
                *(uint32_t*)&g_xp1h[(size_t)row * HD + c] = f2h2(acc[mf][nf][0], acc[mf][nf][1]);
            if (row + 8 < N)
                *(uint32_t*)&g_xp1h[(size_t)(row + 8) * HD + c] = f2h2(acc[mf][nf][2], acc[mf][nf][3]);
        }
    }
#pragma unroll
    for (int r = 0; r < 4; r++) {
#pragma unroll
        for (int off = 1; off < 4; off <<= 1) {
            ps[r] += __shfl_xor_sync(0xffffffffu, ps[r], off);
            pd[r] += __shfl_xor_sync(0xffffffffu, pd[r], off);
        }
    }
    if (tg == 0) {
#pragma unroll
        for (int r = 0; r < 4; r++) {
            int rl = m_base + (r >> 1) * 16 + (r & 1) * 8 + g;
            atomicAdd(&es_s[rl], ps[r]);
            atomicAdd(&ed_s[rl], pd[r]);
        }
    }
    __syncthreads();
    if (tid < 128) {
        int row = blk0 + tid;
        if (row < N) {
            g_es[row] = es_s[tid];
            g_ed[row] = ed_s[tid];
        }
    }
}

// =======================================================================
// Layer-1 fused node kernel — HALF-WARP per node (avg degree ~1.8).
// 16 lanes x 8 fp16 dims (uint4) = 128 dims. 2 nodes per warp.
// All shuffles use PER-HALF masks (halves diverge on edge counts).
// =======================================================================
__global__ void __launch_bounds__(256) k_node1(
    const float* __restrict__ b1, const float* __restrict__ W2, int N)
{
    if (blockIdx.x == 0 && threadIdx.x == 0) g_cnt = 0;   // reset for next run
    int lane = threadIdx.x & 31;
    int sub  = lane >> 4;          // half-warp id (0/1)
    int sl   = lane & 15;          // lane within half
    int node = blockIdx.x * 16 + (threadIdx.x >> 5) * 2 + sub;
    if (node >= N) return;
    int sbase = sub << 4;
    unsigned hmask = 0xFFFFu << sbase;   // this half's shuffle mask

    int r0 = __ldg(&g_rowptr[node]);
    int r1 = __ldg(&g_rowptr[node + 1]);
    float edv = g_ed[node];
    float sw = __expf(lrelu(g_es[node] + edv));

    // self row: 8 fp16 dims per lane
    uint4 su = __ldg((const uint4*)&g_xp1h[(size_t)node * HD] + sl);

    float acc[8] = {0.f, 0.f, 0.f, 0.f, 0.f, 0.f, 0.f, 0.f};
    float den_part = 0.f;
    for (int base = r0; base < r1; base += 16) {
        int e = base + sl;
        float wgt = 0.f; int src = 0;
        if (e < r1) {
            src = g_csr[e];
            wgt = __expf(lrelu(__ldg(&g_es[src]) + edv));
            den_part += wgt;
        }
        int cnt = min(16, r1 - base);
        int j = 0;
        for (; j + 2 <= cnt; j += 2) {
            float w0 = __shfl_sync(hmask, wgt, sbase + j);
            float w1 = __shfl_sync(hmask, wgt, sbase + j + 1);
            int s0 = __shfl_sync(hmask, src, sbase + j);
            int s1 = __shfl_sync(hmask, src, sbase + j + 1);
            uint4 u0 = __ldg((const uint4*)&g_xp1h[(size_t)s0 * HD] + sl);
            uint4 u1 = __ldg((const uint4*)&g_xp1h[(size_t)s1 * HD] + sl);
            {
                float2 f0 = __half22float2(*(__half2*)&u0.x);
                float2 f1 = __half22float2(*(__half2*)&u0.y);
                float2 f2 = __half22float2(*(__half2*)&u0.z);
                float2 f3 = __half22float2(*(__half2*)&u0.w);
                acc[0] += w0 * f0.x; acc[1] += w0 * f0.y;
                acc[2] += w0 * f1.x; acc[3] += w0 * f1.y;
                acc[4] += w0 * f2.x; acc[5] += w0 * f2.y;
                acc[6] += w0 * f3.x; acc[7] += w0 * f3.y;
            }
            {
                float2 f0 = __half22float2(*(__half2*)&u1.x);
                float2 f1 = __half22float2(*(__half2*)&u1.y);
                float2 f2 = __half22float2(*(__half2*)&u1.z);
                float2 f3 = __half22float2(*(__half2*)&u1.w);
                acc[0] += w1 * f0.x; acc[1] += w1 * f0.y;
                acc[2] += w1 * f1.x; acc[3] += w1 * f1.y;
                acc[4] += w1 * f2.x; acc[5] += w1 * f2.y;
                acc[6] += w1 * f3.x; acc[7] += w1 * f3.y;
            }
        }
        for (; j < cnt; j++) {
            float wj = __shfl_sync(hmask, wgt, sbase + j);
            int   sj = __shfl_sync(hmask, src, sbase + j);
            uint4 u = __ldg((const uint4*)&g_xp1h[(size_t)sj * HD] + sl);
            float2 f0 = __half22float2(*(__half2*)&u.x);
            float2 f1 = __half22float2(*(__half2*)&u.y);
            float2 f2 = __half22float2(*(__half2*)&u.z);
            float2 f3 = __half22float2(*(__half2*)&u.w);
            acc[0] += wj * f0.x; acc[1] += wj * f0.y;
            acc[2] += wj * f1.x; acc[3] += wj * f1.y;
            acc[4] += wj * f2.x; acc[5] += wj * f2.y;
            acc[6] += wj * f3.x; acc[7] += wj * f3.y;
        }
    }
#pragma unroll
    for (int off = 8; off; off >>= 1)
        den_part += __shfl_xor_sync(hmask, den_part, off);
    float inv = __frcp_rn(den_part + sw);

    // add self contribution, normalize, fused GEMV
    float s;
    {
        float2 f0 = __half22float2(*(__half2*)&su.x);
        float2 f1 = __half22float2(*(__half2*)&su.y);
        float2 f2 = __half22float2(*(__half2*)&su.z);
        float2 f3 = __half22float2(*(__half2*)&su.w);
        float o[8];
        o[0] = (acc[0] + sw * f0.x) * inv; o[1] = (acc[1] + sw * f0.y) * inv;
        o[2] = (acc[2] + sw * f1.x) * inv; o[3] = (acc[3] + sw * f1.y) * inv;
        o[4] = (acc[4] + sw * f2.x) * inv; o[5] = (acc[5] + sw * f2.y) * inv;
        o[6] = (acc[6] + sw * f3.x) * inv; o[7] = (acc[7] + sw * f3.y) * inv;

        float4 b0 = __ldg((const float4*)&b1[sl * 8]);
        float4 b1v = __ldg((const float4*)&b1[sl * 8 + 4]);
        float4 w0 = __ldg((const float4*)&W2[sl * 8]);
        float4 w1v = __ldg((const float4*)&W2[sl * 8 + 4]);
        s = fmaxf(o[0] + b0.x, 0.f) * w0.x + fmaxf(o[1] + b0.y, 0.f) * w0.y +
            fmaxf(o[2] + b0.z, 0.f) * w0.z + fmaxf(o[3] + b0.w, 0.f) * w0.w +
            fmaxf(o[4] + b1v.x, 0.f) * w1v.x + fmaxf(o[5] + b1v.y, 0.f) * w1v.y +
            fmaxf(o[6] + b1v.z, 0.f) * w1v.z + fmaxf(o[7] + b1v.w, 0.f) * w1v.w;
    }
#pragma unroll
    for (int off = 8; off; off >>= 1) s += __shfl_xor_sync(hmask, s, off);
    if (sl == 0) g_xp2[node] = s;
}

// =======================================================================
// Layer-2 fused node kernel (thread per node, OUT=1), single pass.
// =======================================================================
__global__ void k_node2(const float* __restrict__ as2, const float* __restrict__ ad2,
                        const float* __restrict__ b2, float* __restrict__ out, int N)
{
    int i = blockIdx.x * blockDim.x + threadIdx.x;
    if (i >= N) return;
    float a = __ldg(&as2[0]), b = __ldg(&ad2[0]);
    float xi = g_xp2[i];
    int r0 = g_rowptr[i], r1 = g_rowptr[i + 1];
    float xib = xi * b;
    float sw = __expf(lrelu(xi * a + xib));
    float den = sw, num = sw * xi;
    for (int e = r0; e < r1; e++) {
        float xs = __ldg(&g_xp2[g_csr[e]]);
        float w = __expf(lrelu(xs * a + xib));
        den += w;
        num += w * xs;
    }
    out[i] = num / den + __ldg(&b2[0]);
}

// ---------------- launch ----------------
extern "C" void kernel_launch(void* const* d_in, const int* in_sizes, int n_in,
                              void* d_out, int out_size) {
    const int*   h    = (const int*)d_in[0];
    const int*   ei   = (const int*)d_in[1];
    const int*   nt   = (const int*)d_in[2];
    const float* emb  = (const float*)d_in[3];
    const float* W1   = (const float*)d_in[4];
    const float* as1  = (const float*)d_in[5];
    const float* ad1  = (const float*)d_in[6];
    const float* b1   = (const float*)d_in[7];
    const float* W2   = (const float*)d_in[8];
    const float* as2  = (const float*)d_in[9];
    const float* ad2  = (const float*)d_in[10];
    const float* b2   = (const float*)d_in[11];
    float* out = (float*)d_out;

    int N = in_sizes[0];
    int E = in_sizes[1] / 2;
    int nb = (N + 255) / 256;
    int nscan = (N + SCAN_B - 1) / SCAN_B;

    static cudaStream_t s2 = nullptr;
    static cudaEvent_t evFork = nullptr, evJoin = nullptr;
    if (!s2) {
        cudaStreamCreateWithFlags(&s2, cudaStreamNonBlocking);
        cudaEventCreateWithFlags(&evFork, cudaEventDisableTiming);
        cudaEventCreateWithFlags(&evJoin, cudaEventDisableTiming);
    }

    cudaEventRecord(evFork, 0);
    cudaStreamWaitEvent(s2, evFork, 0);

    // CSR build part 1 (main stream) — launches 1..3
    k_deg<<<1024, 256>>>(ei, nt, E);
    k_scanA<<<nscan, SCAN_B>>>(N);
    k_scanC<<<nb, 256>>>(N);

    // GEMM on s2 — launch 4 (profiled)
    k_gemm1_tc<<<(N + 127) / 128, 256, 0, s2>>>(h, emb, W1, as1, ad1, N);
    cudaEventRecord(evJoin, s2);

    // CSR build part 2 — launch 5
    k_scatter<<<1024, 256>>>();

    cudaStreamWaitEvent(0, evJoin, 0);

    k_node1<<<(N + 15) / 16, 256>>>(b1, W2, N);
    k_node2<<<nb, 256>>>(as2, ad2, b2, out, N);
}